// round 15
// baseline (speedup 1.0000x reference)
#include <cuda_runtime.h>
#include <cuda_fp16.h>

// Problem constants (fixed shapes for this problem instance)
#define N_NODES 100000
#define NUM_E   1600000
#define IN_C    128
#define HID     32
#define HEADS   4
#define H1DIM   128   // HEADS*HID
#define OUT_C   64
#define NEG_SLOPE 0.2f

#define SCAN_B 512
#define SCAN_NBLK ((N_NODES + SCAN_B - 1) / SCAN_B)   // 196
#define NODE_BLOCKS ((N_NODES + 255) / 256)
#define EDGE_BLOCKS ((NUM_E + 255) / 256)
#define GEMM_BLOCKS ((N_NODES + 127) / 128)            // 782

// ---------------- scratch (device globals; no runtime allocation) -----------
__device__ int   g_is64;                 // edge_index dtype flag (1 = int64)
__device__ int   g_src[NUM_E];
__device__ int   g_dst[NUM_E];
__device__ int   g_psrc[NUM_E];          // CSR-by-dst permuted src ids
__device__ int   g_deg[N_NODES];
__device__ int   g_off[N_NODES + 1];
__device__ int   g_cur[N_NODES];
__device__ int   g_bsum[SCAN_B];
__device__ __align__(16) __half g_h1[(size_t)N_NODES * H1DIM];   // fp16 features
__device__ __align__(16) __half g_out1[(size_t)N_NODES * H1DIM]; // fp16 ELU output
__device__ __align__(16) float  g_als1[N_NODES * HEADS];
__device__ __align__(16) float  g_ald1[N_NODES * HEADS];
__device__ __align__(16) __half g_h2[(size_t)N_NODES * OUT_C];   // fp16 features
__device__ __align__(16) float  g_als2[N_NODES];
__device__ __align__(16) float  g_ald2[N_NODES];

__device__ __forceinline__ float lrelu(float x) {
    return x >= 0.0f ? x : NEG_SLOPE * x;
}

__device__ __forceinline__ unsigned int f2tf32(float x) {
    unsigned int r;
    asm("cvt.rna.tf32.f32 %0, %1;" : "=r"(r) : "f"(x));
    return r;
}

// ---------------- CSR build --------------------------------------------------
__global__ void k_zero_detect(const void* __restrict__ ei) {
    if (blockIdx.x == NODE_BLOCKS) {
        __shared__ int ok;
        if (threadIdx.x == 0) ok = 1;
        __syncthreads();
        const long long* p = (const long long*)ei;
        for (int i = threadIdx.x; i < 2048; i += blockDim.x) {
            long long v = p[i];
            if (v < 0 || v >= N_NODES) ok = 0;
        }
        __syncthreads();
        if (threadIdx.x == 0) g_is64 = ok;
        return;
    }
    int i = blockIdx.x * blockDim.x + threadIdx.x;
    if (i < N_NODES) g_deg[i] = 0;
}

__global__ void k_convert_hist(const void* __restrict__ ei) {
    int i = blockIdx.x * blockDim.x + threadIdx.x;
    if (i < NUM_E) {
        int s, d;
        if (g_is64) {
            const long long* p = (const long long*)ei;
            s = (int)p[i];
            d = (int)p[NUM_E + i];
        } else {
            const int* p = (const int*)ei;
            s = p[i];
            d = p[NUM_E + i];
        }
        s = min(max(s, 0), N_NODES - 1);
        d = min(max(d, 0), N_NODES - 1);
        g_src[i] = s;
        g_dst[i] = d;
        atomicAdd(&g_deg[d], 1);
    }
}

__global__ void k_scan1() {
    __shared__ int sh[SCAN_B];
    int tid = threadIdx.x;
    int i = blockIdx.x * SCAN_B + tid;
    int v = (i < N_NODES) ? g_deg[i] : 0;
    sh[tid] = v;
    __syncthreads();
    for (int o = 1; o < SCAN_B; o <<= 1) {
        int t = (tid >= o) ? sh[tid - o] : 0;
        __syncthreads();
        sh[tid] += t;
        __syncthreads();
    }
    if (i < N_NODES) g_off[i] = sh[tid] - v;
    if (tid == SCAN_B - 1) g_bsum[blockIdx.x] = sh[tid];
}

// scan of the 196 block sums folded into the per-node fixup.
__global__ void k_scan23() {
    __shared__ int sh[256];
    __shared__ int sexc[256];
    int tid = threadIdx.x;
    int v = (tid < SCAN_NBLK) ? g_bsum[tid] : 0;
    sh[tid] = v;
    __syncthreads();
    for (int o = 1; o < 256; o <<= 1) {
        int t = (tid >= o) ? sh[tid - o] : 0;
        __syncthreads();
        sh[tid] += t;
        __syncthreads();
    }
    sexc[tid] = sh[tid] - v;
    __syncthreads();
    int i = blockIdx.x * blockDim.x + tid;
    if (i < N_NODES) {
        int o = g_off[i] + sexc[i / SCAN_B];
        g_off[i] = o;
        g_cur[i] = o;
    }
    if (i == 0) g_off[N_NODES] = NUM_E;
}

__device__ __forceinline__ void scatter_body(int bid) {
    int i = bid * 256 + threadIdx.x;
    if (i < NUM_E) {
        int d = g_dst[i];
        int pos = atomicAdd(&g_cur[d], 1);
        g_psrc[pos] = g_src[i];
    }
}

// ---------------- tf32 tensor-core GEMM with fused attention logits ----------
// LAYER 0: g_h1 [N,128](fp16) = x(f32) [N,128] * W1; logits -> g_als1/g_ald1
// LAYER 1: g_h2 [N, 64](fp16) = g_out1(fp16) [N,128] * W2; logits -> g_als2/g_ald2
// mma.sync.aligned.m16n8k8 tf32. 256 threads, BM=128, warps 4(m) x 2(n).
template <int LAYER, int BN>
__device__ __forceinline__ void gemm_body(int bid,
                                          const float* __restrict__ A_param,
                                          const float* __restrict__ B,
                                          const float* __restrict__ a_s,
                                          const float* __restrict__ a_d) {
    constexpr int BM = 128;
    constexpr int BK = 32;
    constexpr int K = 128;
    constexpr int M = N_NODES;
    constexpr int NT = BN / 2 / 8;   // n-tiles per warp (8 or 4)
    constexpr int APAD = 4;

    __half* __restrict__ C = (LAYER == 0) ? (__half*)g_h1 : (__half*)g_h2;

    __shared__ unsigned int Ast[BK][BM + APAD];   // transposed: Ast[k][m]
    __shared__ unsigned int Bs[BK][BN + APAD];    // Bs[k][n]
    __shared__ float sP[BM], sD[BM];              // layer-2 logit combine

    int tid = threadIdx.x;
    int wid = tid >> 5;
    int lane = tid & 31;
    int gid = lane >> 2;     // 0..7
    int tig = lane & 3;      // 0..3
    int warp_m = wid >> 1;   // 0..3
    int warp_n = wid & 1;    // 0..1
    int m0 = warp_m * 32;
    int n0 = warp_n * (BN / 2);
    int row0 = bid * BM;

    if (LAYER == 1 && tid < BM) { sP[tid] = 0.f; sD[tid] = 0.f; }

    float acc[2][NT][4];
#pragma unroll
    for (int mt = 0; mt < 2; mt++)
#pragma unroll
        for (int nt = 0; nt < NT; nt++)
#pragma unroll
            for (int c = 0; c < 4; c++) acc[mt][nt][c] = 0.f;

    for (int k0 = 0; k0 < K; k0 += BK) {
        // fill A tile (BM x BK) transposed, with tf32 convert
#pragma unroll
        for (int idx = tid; idx < BM * (BK / 4); idx += 256) {
            int m = idx >> 3;            // BK/4 == 8
            int kq = idx & 7;
            int gr = row0 + m;
            float4 v = make_float4(0.f, 0.f, 0.f, 0.f);
            if (LAYER == 0) {
                if (gr < M) v = *(const float4*)&A_param[(size_t)gr * K + k0 + kq * 4];
            } else {
                if (gr < M) {
                    uint2 hv = *(const uint2*)&g_out1[(size_t)gr * K + k0 + kq * 4];
                    float2 f0 = __half22float2(*(__half2*)&hv.x);
                    float2 f1 = __half22float2(*(__half2*)&hv.y);
                    v = make_float4(f0.x, f0.y, f1.x, f1.y);
                }
            }
            Ast[kq * 4 + 0][m] = f2tf32(v.x);
            Ast[kq * 4 + 1][m] = f2tf32(v.y);
            Ast[kq * 4 + 2][m] = f2tf32(v.z);
            Ast[kq * 4 + 3][m] = f2tf32(v.w);
        }
        // fill B tile (BK x BN)
#pragma unroll
        for (int idx = tid; idx < BK * (BN / 4); idx += 256) {
            int kk = idx / (BN / 4);
            int cq = idx % (BN / 4);
            float4 v = *(const float4*)&B[(size_t)(k0 + kk) * BN + cq * 4];
            Bs[kk][cq * 4 + 0] = f2tf32(v.x);
            Bs[kk][cq * 4 + 1] = f2tf32(v.y);
            Bs[kk][cq * 4 + 2] = f2tf32(v.z);
            Bs[kk][cq * 4 + 3] = f2tf32(v.w);
        }
        __syncthreads();

#pragma unroll
        for (int ks = 0; ks < BK / 8; ks++) {
            unsigned int a[2][4];
#pragma unroll
            for (int mt = 0; mt < 2; mt++) {
                int mb = m0 + mt * 16 + gid;
                a[mt][0] = Ast[ks * 8 + tig][mb];
                a[mt][1] = Ast[ks * 8 + tig][mb + 8];
                a[mt][2] = Ast[ks * 8 + tig + 4][mb];
                a[mt][3] = Ast[ks * 8 + tig + 4][mb + 8];
            }
#pragma unroll
            for (int nt = 0; nt < NT; nt++) {
                unsigned int b0 = Bs[ks * 8 + tig][n0 + nt * 8 + gid];
                unsigned int b1 = Bs[ks * 8 + tig + 4][n0 + nt * 8 + gid];
#pragma unroll
                for (int mt = 0; mt < 2; mt++) {
                    asm("mma.sync.aligned.m16n8k8.row.col.f32.tf32.tf32.f32 "
                        "{%0,%1,%2,%3}, {%4,%5,%6,%7}, {%8,%9}, {%0,%1,%2,%3};"
                        : "+f"(acc[mt][nt][0]), "+f"(acc[mt][nt][1]),
                          "+f"(acc[mt][nt][2]), "+f"(acc[mt][nt][3])
                        : "r"(a[mt][0]), "r"(a[mt][1]), "r"(a[mt][2]), "r"(a[mt][3]),
                          "r"(b0), "r"(b1));
                }
            }
        }
        __syncthreads();
    }

    // ---- epilogue: store C as fp16 ----
#pragma unroll
    for (int mt = 0; mt < 2; mt++) {
#pragma unroll
        for (int nt = 0; nt < NT; nt++) {
            int col = n0 + nt * 8 + 2 * tig;
            int r0 = row0 + m0 + mt * 16 + gid;
            if (r0 < M)
                *(__half2*)&C[(size_t)r0 * BN + col] =
                    __floats2half2_rn(acc[mt][nt][0], acc[mt][nt][1]);
            if (r0 + 8 < M)
                *(__half2*)&C[(size_t)(r0 + 8) * BN + col] =
                    __floats2half2_rn(acc[mt][nt][2], acc[mt][nt][3]);
        }
    }

    // ---- epilogue: fused attention logits (fp32 accumulators) ----
    if (LAYER == 0) {
        float ps[2][2][2], pd[2][2][2];
#pragma unroll
        for (int mt = 0; mt < 2; mt++)
#pragma unroll
            for (int hf = 0; hf < 2; hf++)
#pragma unroll
                for (int hl = 0; hl < 2; hl++) { ps[mt][hf][hl] = 0.f; pd[mt][hf][hl] = 0.f; }
#pragma unroll
        for (int mt = 0; mt < 2; mt++)
#pragma unroll
            for (int nt = 0; nt < NT; nt++) {
                int col = n0 + nt * 8 + 2 * tig;
                int hl = nt >> 2;
                float s0 = a_s[col], s1 = a_s[col + 1];
                float d0 = a_d[col], d1 = a_d[col + 1];
                ps[mt][0][hl] += acc[mt][nt][0] * s0 + acc[mt][nt][1] * s1;
                ps[mt][1][hl] += acc[mt][nt][2] * s0 + acc[mt][nt][3] * s1;
                pd[mt][0][hl] += acc[mt][nt][0] * d0 + acc[mt][nt][1] * d1;
                pd[mt][1][hl] += acc[mt][nt][2] * d0 + acc[mt][nt][3] * d1;
            }
#pragma unroll
        for (int mt = 0; mt < 2; mt++)
#pragma unroll
            for (int hf = 0; hf < 2; hf++)
#pragma unroll
                for (int hl = 0; hl < 2; hl++) {
                    float p = ps[mt][hf][hl], q = pd[mt][hf][hl];
                    p += __shfl_xor_sync(0xffffffffu, p, 1);
                    p += __shfl_xor_sync(0xffffffffu, p, 2);
                    q += __shfl_xor_sync(0xffffffffu, q, 1);
                    q += __shfl_xor_sync(0xffffffffu, q, 2);
                    ps[mt][hf][hl] = p; pd[mt][hf][hl] = q;
                }
        if (tig == 0) {
#pragma unroll
            for (int mt = 0; mt < 2; mt++)
#pragma unroll
                for (int hf = 0; hf < 2; hf++) {
                    int row = row0 + m0 + mt * 16 + hf * 8 + gid;
                    if (row < M) {
#pragma unroll
                        for (int hl = 0; hl < 2; hl++) {
                            int head = warp_n * 2 + hl;
                            g_als1[row * HEADS + head] = ps[mt][hf][hl];
                            g_ald1[row * HEADS + head] = pd[mt][hf][hl];
                        }
                    }
                }
        }
    } else {
        float ps[2][2], pd[2][2];
#pragma unroll
        for (int mt = 0; mt < 2; mt++)
#pragma unroll
            for (int hf = 0; hf < 2; hf++) { ps[mt][hf] = 0.f; pd[mt][hf] = 0.f; }
#pragma unroll
        for (int mt = 0; mt < 2; mt++)
#pragma unroll
            for (int nt = 0; nt < NT; nt++) {
                int col = n0 + nt * 8 + 2 * tig;
                float s0 = a_s[col], s1 = a_s[col + 1];
                float d0 = a_d[col], d1 = a_d[col + 1];
                ps[mt][0] += acc[mt][nt][0] * s0 + acc[mt][nt][1] * s1;
                ps[mt][1] += acc[mt][nt][2] * s0 + acc[mt][nt][3] * s1;
                pd[mt][0] += acc[mt][nt][0] * d0 + acc[mt][nt][1] * d1;
                pd[mt][1] += acc[mt][nt][2] * d0 + acc[mt][nt][3] * d1;
            }
#pragma unroll
        for (int mt = 0; mt < 2; mt++)
#pragma unroll
            for (int hf = 0; hf < 2; hf++) {
                float p = ps[mt][hf], q = pd[mt][hf];
                p += __shfl_xor_sync(0xffffffffu, p, 1);
                p += __shfl_xor_sync(0xffffffffu, p, 2);
                q += __shfl_xor_sync(0xffffffffu, q, 1);
                q += __shfl_xor_sync(0xffffffffu, q, 2);
                if (tig == 0) {
                    int rl = m0 + mt * 16 + hf * 8 + gid;
                    atomicAdd(&sP[rl], p);
                    atomicAdd(&sD[rl], q);
                }
            }
        __syncthreads();
        if (tid < BM) {
            int row = row0 + tid;
            if (row < M) {
                g_als2[row] = sP[tid];
                g_ald2[row] = sD[tid];
            }
        }
    }
}

// Fused launch: blocks [0, GEMM_BLOCKS) do layer-1 GEMM+logits; the rest do
// the CSR scatter. Both depend only on already-computed state, so they
// overlap on the chip instead of serializing as two launches.
__global__ void __launch_bounds__(256) k_l1_fused(const float* __restrict__ x,
                                                  const float* __restrict__ W1,
                                                  const float* __restrict__ a_s,
                                                  const float* __restrict__ a_d) {
    if (blockIdx.x < GEMM_BLOCKS) {
        gemm_body<0, 128>(blockIdx.x, x, W1, a_s, a_d);
    } else {
        scatter_body(blockIdx.x - GEMM_BLOCKS);
    }
}

__global__ void __launch_bounds__(256) k_gemm2(const float* __restrict__ W2,
                                               const float* __restrict__ a_s,
                                               const float* __restrict__ a_d) {
    gemm_body<1, 64>(blockIdx.x, nullptr, W2, a_s, a_d);
}

// ---------------- aggregation (warp per destination node, single pass) ------
__global__ void k_agg1(const float* __restrict__ bias) {
    int w = (blockIdx.x * blockDim.x + threadIdx.x) >> 5;
    int lane = threadIdx.x & 31;
    if (w >= N_NODES) return;
    int beg = g_off[w], end = g_off[w + 1];
    int head = lane >> 3;
    float adh = g_ald1[w * HEADS + head];

    float4 acc = make_float4(0.f, 0.f, 0.f, 0.f);
    float s = 0.f;
    const uint2* hp = (const uint2*)g_h1;   // 4 halves per uint2; row = 32 uint2
#pragma unroll 2
    for (int j = beg; j < end; ++j) {
        int src = g_psrc[j];
        float als = g_als1[src * HEADS + head];
        float e = __expf(lrelu(als + adh));
        uint2 hv = hp[(size_t)src * (H1DIM / 4) + lane];
        float2 f0 = __half22float2(*(__half2*)&hv.x);
        float2 f1 = __half22float2(*(__half2*)&hv.y);
        acc.x += f0.x * e; acc.y += f0.y * e; acc.z += f1.x * e; acc.w += f1.y * e;
        s += e;
    }
    float inv = 1.0f / (s + 1e-16f);

    float4 bv = ((const float4*)bias)[lane];
    float4 v;
    v.x = acc.x * inv + bv.x; v.y = acc.y * inv + bv.y;
    v.z = acc.z * inv + bv.z; v.w = acc.w * inv + bv.w;
    v.x = v.x > 0.f ? v.x : expm1f(v.x);
    v.y = v.y > 0.f ? v.y : expm1f(v.y);
    v.z = v.z > 0.f ? v.z : expm1f(v.z);
    v.w = v.w > 0.f ? v.w : expm1f(v.w);
    __half2 p0 = __floats2half2_rn(v.x, v.y);
    __half2 p1 = __floats2half2_rn(v.z, v.w);
    uint2 st;
    st.x = *(unsigned int*)&p0;
    st.y = *(unsigned int*)&p1;
    ((uint2*)g_out1)[(size_t)w * (H1DIM / 4) + lane] = st;
}

// Layer 2: 64 ch -> 16 lanes x 4 halves -> 2 edges per warp-iter.
__global__ void k_agg2(const float* __restrict__ bias, float* __restrict__ out) {
    int w = (blockIdx.x * blockDim.x + threadIdx.x) >> 5;
    int lane = threadIdx.x & 31;
    if (w >= N_NODES) return;
    int beg = g_off[w], end = g_off[w + 1];
    int half = lane >> 4;   // which edge of the pair
    int sl = lane & 15;     // channel group within row
    float ad = g_ald2[w];

    float4 acc = make_float4(0.f, 0.f, 0.f, 0.f);
    float s = 0.f;
    const uint2* hp = (const uint2*)g_h2;   // row = 16 uint2
    for (int j = beg + half; j < end; j += 2) {
        int src = g_psrc[j];
        float e = __expf(lrelu(g_als2[src] + ad));
        uint2 hv = hp[(size_t)src * (OUT_C / 4) + sl];
        float2 f0 = __half22float2(*(__half2*)&hv.x);
        float2 f1 = __half22float2(*(__half2*)&hv.y);
        acc.x += f0.x * e; acc.y += f0.y * e; acc.z += f1.x * e; acc.w += f1.y * e;
        s += e;
    }
    s += __shfl_xor_sync(0xffffffffu, s, 16);
    acc.x += __shfl_xor_sync(0xffffffffu, acc.x, 16);
    acc.y += __shfl_xor_sync(0xffffffffu, acc.y, 16);
    acc.z += __shfl_xor_sync(0xffffffffu, acc.z, 16);
    acc.w += __shfl_xor_sync(0xffffffffu, acc.w, 16);
    if (half == 0) {
        float inv = 1.0f / (s + 1e-16f);
        float4 bv = ((const float4*)bias)[sl];
        float4 v;
        v.x = acc.x * inv + bv.x; v.y = acc.y * inv + bv.y;
        v.z = acc.z * inv + bv.z; v.w = acc.w * inv + bv.w;
        ((float4*)out)[(size_t)w * (OUT_C / 4) + sl] = v;
    }
}

// ---------------- launch -----------------------------------------------------
extern "C" void kernel_launch(void* const* d_in, const int* in_sizes, int n_in,
                              void* d_out, int out_size) {
    const float*      x      = (const float*)d_in[0];
    const void*       eidx   = d_in[1];               // int32 or int64, detected on device
    const float*      W1     = (const float*)d_in[2];
    const float*      a_src1 = (const float*)d_in[3];
    const float*      a_dst1 = (const float*)d_in[4];
    const float*      b1     = (const float*)d_in[5];
    const float*      W2     = (const float*)d_in[6];
    const float*      a_src2 = (const float*)d_in[7];
    const float*      a_dst2 = (const float*)d_in[8];
    const float*      b2     = (const float*)d_in[9];
    float*            out    = (float*)d_out;

    const int warp_blocks = (N_NODES * 32 + 255) / 256;

    // CSR histogram + offsets
    k_zero_detect<<<NODE_BLOCKS + 1, 256>>>(eidx);
    k_convert_hist<<<EDGE_BLOCKS, 256>>>(eidx);
    k_scan1<<<SCAN_NBLK, SCAN_B>>>();
    k_scan23<<<NODE_BLOCKS, 256>>>();

    // Layer-1 GEMM+logits overlapped with CSR scatter (independent work)
    k_l1_fused<<<GEMM_BLOCKS + EDGE_BLOCKS, 256>>>(x, W1, a_src1, a_dst1);
    k_agg1<<<warp_blocks, 256>>>(b1);

    // Layer 2
    k_gemm2<<<GEMM_BLOCKS, 256>>>(W2, a_src2, a_dst2);
    k_agg2<<<warp_blocks, 256>>>(b2, out);
}

// round 16
// speedup vs baseline: 1.0848x; 1.0848x over previous
#include <cuda_runtime.h>
#include <cuda_fp16.h>

// Problem constants (fixed shapes for this problem instance)
#define N_NODES 100000
#define NUM_E   1600000
#define IN_C    128
#define HID     32
#define HEADS   4
#define H1DIM   128   // HEADS*HID
#define OUT_C   64
#define NEG_SLOPE 0.2f

#define SCAN_B 512
#define SCAN_NBLK ((N_NODES + SCAN_B - 1) / SCAN_B)   // 196
#define NODE_BLOCKS ((N_NODES + 255) / 256)
#define EDGE_BLOCKS ((NUM_E + 255) / 256)
#define GEMM_BLOCKS ((N_NODES + 127) / 128)            // 782

// ---------------- scratch (device globals; no runtime allocation) -----------
__device__ int   g_is64;                 // edge_index dtype flag (1 = int64)
__device__ int   g_src[NUM_E];
__device__ int   g_dst[NUM_E];
__device__ int   g_psrc[NUM_E];          // CSR-by-dst permuted src ids
__device__ int   g_deg[N_NODES];
__device__ int   g_off[N_NODES + 1];
__device__ int   g_cur[N_NODES];
__device__ int   g_bsum[SCAN_B];
__device__ __align__(16) __half g_h1[(size_t)N_NODES * H1DIM];   // fp16 features
__device__ __align__(16) __half g_out1[(size_t)N_NODES * H1DIM]; // fp16 ELU output
__device__ __align__(16) float  g_als1[N_NODES * HEADS];
__device__ __align__(16) float  g_ald1[N_NODES * HEADS];
__device__ __align__(16) __half g_h2[(size_t)N_NODES * OUT_C];   // fp16 features
__device__ __align__(16) float  g_als2[N_NODES];
__device__ __align__(16) float  g_ald2[N_NODES];

__device__ __forceinline__ float lrelu(float x) {
    return x >= 0.0f ? x : NEG_SLOPE * x;
}

__device__ __forceinline__ unsigned int f2tf32(float x) {
    unsigned int r;
    asm("cvt.rna.tf32.f32 %0, %1;" : "=r"(r) : "f"(x));
    return r;
}

// ---------------- CSR build --------------------------------------------------
__global__ void k_zero_detect(const void* __restrict__ ei) {
    if (blockIdx.x == NODE_BLOCKS) {
        __shared__ int ok;
        if (threadIdx.x == 0) ok = 1;
        __syncthreads();
        const long long* p = (const long long*)ei;
        for (int i = threadIdx.x; i < 2048; i += blockDim.x) {
            long long v = p[i];
            if (v < 0 || v >= N_NODES) ok = 0;
        }
        __syncthreads();
        if (threadIdx.x == 0) g_is64 = ok;
        return;
    }
    int i = blockIdx.x * blockDim.x + threadIdx.x;
    if (i < N_NODES) g_deg[i] = 0;
}

__global__ void k_convert_hist(const void* __restrict__ ei) {
    int i = blockIdx.x * blockDim.x + threadIdx.x;
    if (i < NUM_E) {
        int s, d;
        if (g_is64) {
            const long long* p = (const long long*)ei;
            s = (int)p[i];
            d = (int)p[NUM_E + i];
        } else {
            const int* p = (const int*)ei;
            s = p[i];
            d = p[NUM_E + i];
        }
        s = min(max(s, 0), N_NODES - 1);
        d = min(max(d, 0), N_NODES - 1);
        g_src[i] = s;
        g_dst[i] = d;
        atomicAdd(&g_deg[d], 1);
    }
}

__global__ void k_scan1() {
    __shared__ int sh[SCAN_B];
    int tid = threadIdx.x;
    int i = blockIdx.x * SCAN_B + tid;
    int v = (i < N_NODES) ? g_deg[i] : 0;
    sh[tid] = v;
    __syncthreads();
    for (int o = 1; o < SCAN_B; o <<= 1) {
        int t = (tid >= o) ? sh[tid - o] : 0;
        __syncthreads();
        sh[tid] += t;
        __syncthreads();
    }
    if (i < N_NODES) g_off[i] = sh[tid] - v;
    if (tid == SCAN_B - 1) g_bsum[blockIdx.x] = sh[tid];
}

// scan of the 196 block sums folded into the per-node fixup.
__global__ void k_scan23() {
    __shared__ int sh[256];
    __shared__ int sexc[256];
    int tid = threadIdx.x;
    int v = (tid < SCAN_NBLK) ? g_bsum[tid] : 0;
    sh[tid] = v;
    __syncthreads();
    for (int o = 1; o < 256; o <<= 1) {
        int t = (tid >= o) ? sh[tid - o] : 0;
        __syncthreads();
        sh[tid] += t;
        __syncthreads();
    }
    sexc[tid] = sh[tid] - v;
    __syncthreads();
    int i = blockIdx.x * blockDim.x + tid;
    if (i < N_NODES) {
        int o = g_off[i] + sexc[i / SCAN_B];
        g_off[i] = o;
        g_cur[i] = o;
    }
    if (i == 0) g_off[N_NODES] = NUM_E;
}

__global__ void k_scatter() {
    int i = blockIdx.x * blockDim.x + threadIdx.x;
    if (i < NUM_E) {
        int d = g_dst[i];
        int pos = atomicAdd(&g_cur[d], 1);
        g_psrc[pos] = g_src[i];
    }
}

// ---------------- tf32 tensor-core GEMM with fused attention logits ----------
// LAYER 0: g_h1 [N,128](fp16) = x(f32) [N,128] * W1; logits -> g_als1/g_ald1
// LAYER 1: g_h2 [N, 64](fp16) = g_out1(fp16) [N,128] * W2; logits -> g_als2/g_ald2
// mma.sync.aligned.m16n8k8 tf32. 256 threads, BM=128, warps 4(m) x 2(n).
template <int LAYER, int BN>
__global__ void __launch_bounds__(256) k_gemm_tc(const float* __restrict__ A_param,
                                                 const float* __restrict__ B,
                                                 const float* __restrict__ a_s,
                                                 const float* __restrict__ a_d) {
    constexpr int BM = 128;
    constexpr int BK = 32;
    constexpr int K = 128;
    constexpr int M = N_NODES;
    constexpr int NT = BN / 2 / 8;   // n-tiles per warp (8 or 4)
    constexpr int APAD = 4;

    __half* __restrict__ C = (LAYER == 0) ? (__half*)g_h1 : (__half*)g_h2;

    __shared__ unsigned int Ast[BK][BM + APAD];   // transposed: Ast[k][m]
    __shared__ unsigned int Bs[BK][BN + APAD];    // Bs[k][n]
    __shared__ float sP[BM], sD[BM];              // layer-2 logit combine

    int tid = threadIdx.x;
    int wid = tid >> 5;
    int lane = tid & 31;
    int gid = lane >> 2;     // 0..7
    int tig = lane & 3;      // 0..3
    int warp_m = wid >> 1;   // 0..3
    int warp_n = wid & 1;    // 0..1
    int m0 = warp_m * 32;
    int n0 = warp_n * (BN / 2);
    int row0 = blockIdx.x * BM;

    if (LAYER == 1 && tid < BM) { sP[tid] = 0.f; sD[tid] = 0.f; }

    float acc[2][NT][4];
#pragma unroll
    for (int mt = 0; mt < 2; mt++)
#pragma unroll
        for (int nt = 0; nt < NT; nt++)
#pragma unroll
            for (int c = 0; c < 4; c++) acc[mt][nt][c] = 0.f;

    for (int k0 = 0; k0 < K; k0 += BK) {
        // fill A tile (BM x BK) transposed, with tf32 convert
#pragma unroll
        for (int idx = tid; idx < BM * (BK / 4); idx += 256) {
            int m = idx >> 3;            // BK/4 == 8
            int kq = idx & 7;
            int gr = row0 + m;
            float4 v = make_float4(0.f, 0.f, 0.f, 0.f);
            if (LAYER == 0) {
                if (gr < M) v = *(const float4*)&A_param[(size_t)gr * K + k0 + kq * 4];
            } else {
                if (gr < M) {
                    uint2 hv = *(const uint2*)&g_out1[(size_t)gr * K + k0 + kq * 4];
                    float2 f0 = __half22float2(*(__half2*)&hv.x);
                    float2 f1 = __half22float2(*(__half2*)&hv.y);
                    v = make_float4(f0.x, f0.y, f1.x, f1.y);
                }
            }
            Ast[kq * 4 + 0][m] = f2tf32(v.x);
            Ast[kq * 4 + 1][m] = f2tf32(v.y);
            Ast[kq * 4 + 2][m] = f2tf32(v.z);
            Ast[kq * 4 + 3][m] = f2tf32(v.w);
        }
        // fill B tile (BK x BN)
#pragma unroll
        for (int idx = tid; idx < BK * (BN / 4); idx += 256) {
            int kk = idx / (BN / 4);
            int cq = idx % (BN / 4);
            float4 v = *(const float4*)&B[(size_t)(k0 + kk) * BN + cq * 4];
            Bs[kk][cq * 4 + 0] = f2tf32(v.x);
            Bs[kk][cq * 4 + 1] = f2tf32(v.y);
            Bs[kk][cq * 4 + 2] = f2tf32(v.z);
            Bs[kk][cq * 4 + 3] = f2tf32(v.w);
        }
        __syncthreads();

#pragma unroll
        for (int ks = 0; ks < BK / 8; ks++) {
            unsigned int a[2][4];
#pragma unroll
            for (int mt = 0; mt < 2; mt++) {
                int mb = m0 + mt * 16 + gid;
                a[mt][0] = Ast[ks * 8 + tig][mb];
                a[mt][1] = Ast[ks * 8 + tig][mb + 8];
                a[mt][2] = Ast[ks * 8 + tig + 4][mb];
                a[mt][3] = Ast[ks * 8 + tig + 4][mb + 8];
            }
#pragma unroll
            for (int nt = 0; nt < NT; nt++) {
                unsigned int b0 = Bs[ks * 8 + tig][n0 + nt * 8 + gid];
                unsigned int b1 = Bs[ks * 8 + tig + 4][n0 + nt * 8 + gid];
#pragma unroll
                for (int mt = 0; mt < 2; mt++) {
                    asm("mma.sync.aligned.m16n8k8.row.col.f32.tf32.tf32.f32 "
                        "{%0,%1,%2,%3}, {%4,%5,%6,%7}, {%8,%9}, {%0,%1,%2,%3};"
                        : "+f"(acc[mt][nt][0]), "+f"(acc[mt][nt][1]),
                          "+f"(acc[mt][nt][2]), "+f"(acc[mt][nt][3])
                        : "r"(a[mt][0]), "r"(a[mt][1]), "r"(a[mt][2]), "r"(a[mt][3]),
                          "r"(b0), "r"(b1));
                }
            }
        }
        __syncthreads();
    }

    // ---- epilogue: store C as fp16 ----
#pragma unroll
    for (int mt = 0; mt < 2; mt++) {
#pragma unroll
        for (int nt = 0; nt < NT; nt++) {
            int col = n0 + nt * 8 + 2 * tig;
            int r0 = row0 + m0 + mt * 16 + gid;
            if (r0 < M)
                *(__half2*)&C[(size_t)r0 * BN + col] =
                    __floats2half2_rn(acc[mt][nt][0], acc[mt][nt][1]);
            if (r0 + 8 < M)
                *(__half2*)&C[(size_t)(r0 + 8) * BN + col] =
                    __floats2half2_rn(acc[mt][nt][2], acc[mt][nt][3]);
        }
    }

    // ---- epilogue: fused attention logits (fp32 accumulators) ----
    if (LAYER == 0) {
        float ps[2][2][2], pd[2][2][2];
#pragma unroll
        for (int mt = 0; mt < 2; mt++)
#pragma unroll
            for (int hf = 0; hf < 2; hf++)
#pragma unroll
                for (int hl = 0; hl < 2; hl++) { ps[mt][hf][hl] = 0.f; pd[mt][hf][hl] = 0.f; }
#pragma unroll
        for (int mt = 0; mt < 2; mt++)
#pragma unroll
            for (int nt = 0; nt < NT; nt++) {
                int col = n0 + nt * 8 + 2 * tig;
                int hl = nt >> 2;
                float s0 = a_s[col], s1 = a_s[col + 1];
                float d0 = a_d[col], d1 = a_d[col + 1];
                ps[mt][0][hl] += acc[mt][nt][0] * s0 + acc[mt][nt][1] * s1;
                ps[mt][1][hl] += acc[mt][nt][2] * s0 + acc[mt][nt][3] * s1;
                pd[mt][0][hl] += acc[mt][nt][0] * d0 + acc[mt][nt][1] * d1;
                pd[mt][1][hl] += acc[mt][nt][2] * d0 + acc[mt][nt][3] * d1;
            }
#pragma unroll
        for (int mt = 0; mt < 2; mt++)
#pragma unroll
            for (int hf = 0; hf < 2; hf++)
#pragma unroll
                for (int hl = 0; hl < 2; hl++) {
                    float p = ps[mt][hf][hl], q = pd[mt][hf][hl];
                    p += __shfl_xor_sync(0xffffffffu, p, 1);
                    p += __shfl_xor_sync(0xffffffffu, p, 2);
                    q += __shfl_xor_sync(0xffffffffu, q, 1);
                    q += __shfl_xor_sync(0xffffffffu, q, 2);
                    ps[mt][hf][hl] = p; pd[mt][hf][hl] = q;
                }
        if (tig == 0) {
#pragma unroll
            for (int mt = 0; mt < 2; mt++)
#pragma unroll
                for (int hf = 0; hf < 2; hf++) {
                    int row = row0 + m0 + mt * 16 + hf * 8 + gid;
                    if (row < M) {
#pragma unroll
                        for (int hl = 0; hl < 2; hl++) {
                            int head = warp_n * 2 + hl;
                            g_als1[row * HEADS + head] = ps[mt][hf][hl];
                            g_ald1[row * HEADS + head] = pd[mt][hf][hl];
                        }
                    }
                }
        }
    } else {
        float ps[2][2], pd[2][2];
#pragma unroll
        for (int mt = 0; mt < 2; mt++)
#pragma unroll
            for (int hf = 0; hf < 2; hf++) { ps[mt][hf] = 0.f; pd[mt][hf] = 0.f; }
#pragma unroll
        for (int mt = 0; mt < 2; mt++)
#pragma unroll
            for (int nt = 0; nt < NT; nt++) {
                int col = n0 + nt * 8 + 2 * tig;
                float s0 = a_s[col], s1 = a_s[col + 1];
                float d0 = a_d[col], d1 = a_d[col + 1];
                ps[mt][0] += acc[mt][nt][0] * s0 + acc[mt][nt][1] * s1;
                ps[mt][1] += acc[mt][nt][2] * s0 + acc[mt][nt][3] * s1;
                pd[mt][0] += acc[mt][nt][0] * d0 + acc[mt][nt][1] * d1;
                pd[mt][1] += acc[mt][nt][2] * d0 + acc[mt][nt][3] * d1;
            }
#pragma unroll
        for (int mt = 0; mt < 2; mt++)
#pragma unroll
            for (int hf = 0; hf < 2; hf++) {
                float p = ps[mt][hf], q = pd[mt][hf];
                p += __shfl_xor_sync(0xffffffffu, p, 1);
                p += __shfl_xor_sync(0xffffffffu, p, 2);
                q += __shfl_xor_sync(0xffffffffu, q, 1);
                q += __shfl_xor_sync(0xffffffffu, q, 2);
                if (tig == 0) {
                    int rl = m0 + mt * 16 + hf * 8 + gid;
                    atomicAdd(&sP[rl], p);
                    atomicAdd(&sD[rl], q);
                }
            }
        __syncthreads();
        if (tid < BM) {
            int row = row0 + tid;
            if (row < M) {
                g_als2[row] = sP[tid];
                g_ald2[row] = sD[tid];
            }
        }
    }
}

// ---------------- aggregation (warp per destination node, wide lanes) -------
// Layer 1: fp16 row = 256B = 16 lanes x uint4. Lanes 0-15 handle edge j,
// lanes 16-31 edge j+1 -> 2 edges per warp-iter, 3 warp-LDGs per 2 edges
// (the kernels are LSU-issue-bound, not byte-bound; see R14/R16 post-mortems).
__global__ void k_agg1(const float* __restrict__ bias) {
    int w = (blockIdx.x * blockDim.x + threadIdx.x) >> 5;
    int lane = threadIdx.x & 31;
    if (w >= N_NODES) return;
    int beg = g_off[w], end = g_off[w + 1];
    int half = lane >> 4;    // which edge of the pair
    int sl = lane & 15;      // 16B chunk within row (8 channels)
    int head = sl >> 2;      // 32 channels per head / 8 per lane
    float adh = g_ald1[w * HEADS + head];

    float acc[8];
#pragma unroll
    for (int c = 0; c < 8; c++) acc[c] = 0.f;
    float s = 0.f;
    const uint4* hp = (const uint4*)g_h1;   // row = 16 uint4
    for (int j = beg + half; j < end; j += 2) {
        int src = g_psrc[j];
        float e = __expf(lrelu(g_als1[src * HEADS + head] + adh));
        uint4 hv = hp[(size_t)src * (H1DIM / 8) + sl];
        float2 f0 = __half22float2(*(__half2*)&hv.x);
        float2 f1 = __half22float2(*(__half2*)&hv.y);
        float2 f2 = __half22float2(*(__half2*)&hv.z);
        float2 f3 = __half22float2(*(__half2*)&hv.w);
        acc[0] += f0.x * e; acc[1] += f0.y * e;
        acc[2] += f1.x * e; acc[3] += f1.y * e;
        acc[4] += f2.x * e; acc[5] += f2.y * e;
        acc[6] += f3.x * e; acc[7] += f3.y * e;
        s += e;
    }
    // combine the two edge-halves (same head per sl in both halves)
    s += __shfl_xor_sync(0xffffffffu, s, 16);
#pragma unroll
    for (int c = 0; c < 8; c++) acc[c] += __shfl_xor_sync(0xffffffffu, acc[c], 16);

    if (half == 0) {
        float inv = 1.0f / (s + 1e-16f);
        float4 b0 = ((const float4*)bias)[sl * 2];
        float4 b1 = ((const float4*)bias)[sl * 2 + 1];
        float v[8];
        v[0] = acc[0] * inv + b0.x; v[1] = acc[1] * inv + b0.y;
        v[2] = acc[2] * inv + b0.z; v[3] = acc[3] * inv + b0.w;
        v[4] = acc[4] * inv + b1.x; v[5] = acc[5] * inv + b1.y;
        v[6] = acc[6] * inv + b1.z; v[7] = acc[7] * inv + b1.w;
#pragma unroll
        for (int c = 0; c < 8; c++) v[c] = v[c] > 0.f ? v[c] : expm1f(v[c]);
        __half2 p0 = __floats2half2_rn(v[0], v[1]);
        __half2 p1 = __floats2half2_rn(v[2], v[3]);
        __half2 p2 = __floats2half2_rn(v[4], v[5]);
        __half2 p3 = __floats2half2_rn(v[6], v[7]);
        uint4 st;
        st.x = *(unsigned int*)&p0; st.y = *(unsigned int*)&p1;
        st.z = *(unsigned int*)&p2; st.w = *(unsigned int*)&p3;
        ((uint4*)g_out1)[(size_t)w * (H1DIM / 8) + sl] = st;
    }
}

// Layer 2: fp16 row = 128B = 8 lanes x uint4 -> 4 edges per warp-iter.
__global__ void k_agg2(const float* __restrict__ bias, float* __restrict__ out) {
    int w = (blockIdx.x * blockDim.x + threadIdx.x) >> 5;
    int lane = threadIdx.x & 31;
    if (w >= N_NODES) return;
    int beg = g_off[w], end = g_off[w + 1];
    int quarter = lane >> 3;  // which edge of the four
    int sl = lane & 7;        // 16B chunk within row (8 channels)
    float ad = g_ald2[w];

    float acc[8];
#pragma unroll
    for (int c = 0; c < 8; c++) acc[c] = 0.f;
    float s = 0.f;
    const uint4* hp = (const uint4*)g_h2;   // row = 8 uint4
    for (int j = beg + quarter; j < end; j += 4) {
        int src = g_psrc[j];
        float e = __expf(lrelu(g_als2[src] + ad));
        uint4 hv = hp[(size_t)src * (OUT_C / 8) + sl];
        float2 f0 = __half22float2(*(__half2*)&hv.x);
        float2 f1 = __half22float2(*(__half2*)&hv.y);
        float2 f2 = __half22float2(*(__half2*)&hv.z);
        float2 f3 = __half22float2(*(__half2*)&hv.w);
        acc[0] += f0.x * e; acc[1] += f0.y * e;
        acc[2] += f1.x * e; acc[3] += f1.y * e;
        acc[4] += f2.x * e; acc[5] += f2.y * e;
        acc[6] += f3.x * e; acc[7] += f3.y * e;
        s += e;
    }
    // combine the four edge-quarters (quarter lives in lane bits 3 and 4)
    s += __shfl_xor_sync(0xffffffffu, s, 8);
    s += __shfl_xor_sync(0xffffffffu, s, 16);
#pragma unroll
    for (int c = 0; c < 8; c++) {
        acc[c] += __shfl_xor_sync(0xffffffffu, acc[c], 8);
        acc[c] += __shfl_xor_sync(0xffffffffu, acc[c], 16);
    }

    if (quarter == 0) {
        float inv = 1.0f / (s + 1e-16f);
        float4 b0 = ((const float4*)bias)[sl * 2];
        float4 b1 = ((const float4*)bias)[sl * 2 + 1];
        float4 v0, v1;
        v0.x = acc[0] * inv + b0.x; v0.y = acc[1] * inv + b0.y;
        v0.z = acc[2] * inv + b0.z; v0.w = acc[3] * inv + b0.w;
        v1.x = acc[4] * inv + b1.x; v1.y = acc[5] * inv + b1.y;
        v1.z = acc[6] * inv + b1.z; v1.w = acc[7] * inv + b1.w;
        ((float4*)out)[(size_t)w * (OUT_C / 4) + sl * 2] = v0;
        ((float4*)out)[(size_t)w * (OUT_C / 4) + sl * 2 + 1] = v1;
    }
}

// ---------------- launch -----------------------------------------------------
extern "C" void kernel_launch(void* const* d_in, const int* in_sizes, int n_in,
                              void* d_out, int out_size) {
    const float*      x      = (const float*)d_in[0];
    const void*       eidx   = d_in[1];               // int32 or int64, detected on device
    const float*      W1     = (const float*)d_in[2];
    const float*      a_src1 = (const float*)d_in[3];
    const float*      a_dst1 = (const float*)d_in[4];
    const float*      b1     = (const float*)d_in[5];
    const float*      W2     = (const float*)d_in[6];
    const float*      a_src2 = (const float*)d_in[7];
    const float*      a_dst2 = (const float*)d_in[8];
    const float*      b2     = (const float*)d_in[9];
    float*            out    = (float*)d_out;

    const int warp_blocks = (N_NODES * 32 + 255) / 256;

    // CSR build
    k_zero_detect<<<NODE_BLOCKS + 1, 256>>>(eidx);
    k_convert_hist<<<EDGE_BLOCKS, 256>>>(eidx);
    k_scan1<<<SCAN_NBLK, SCAN_B>>>();
    k_scan23<<<NODE_BLOCKS, 256>>>();
    k_scatter<<<EDGE_BLOCKS, 256>>>();

    // Layer 1 (GEMM + fused logits)
    k_gemm_tc<0, 128><<<GEMM_BLOCKS, 256>>>(x, W1, a_src1, a_dst1);
    k_agg1<<<warp_blocks, 256>>>(b1);

    // Layer 2 (GEMM + fused logits)
    k_gemm_tc<1, 64><<<GEMM_BLOCKS, 256>>>(nullptr, W2, a_src2, a_dst2);
    k_agg2<<<warp_blocks, 256>>>(b2, out);
}